// round 13
// baseline (speedup 1.0000x reference)
#include <cuda_runtime.h>
#include <math.h>
#include <float.h>

#define DELTA 1e-6f
#define Bb 128
#define Mm 512
#define Ww 128
#define Rr 4
#define INP 1024
#define NOUT 919
#define SPLITK 8
#define LSPLIT 4
#define MSPLIT 4
#define FSPLIT 4

// ---------------- scratch (static device globals; no allocation) ----------------
__device__ float g_part[SPLITK * Bb * NOUT];
__device__ float g_act[Bb * NOUT];
__device__ float g_wsc[Bb * Mm];
__device__ float g_alloc[Bb * Mm];
__device__ float g_ww[Bb * Mm];
__device__ float g_norm_new[Bb * Mm];
__device__ float g_dots[Bb * Rr * Mm];
__device__ float g_cw[Bb * Rr * Mm];
__device__ float g_fwd[Bb * Rr * Mm];
__device__ float g_bwdp[(size_t)LSPLIT * Bb * Rr * Mm];
__device__ float g_outp[(size_t)FSPLIT * Bb * Rr * Ww];

struct WPtrs { const float* W[10]; const float* bia[10]; };

// ---------------- reductions ----------------
__device__ __forceinline__ float warpReduceSum(float v) {
    #pragma unroll
    for (int o = 16; o > 0; o >>= 1) v += __shfl_down_sync(0xffffffffu, v, o);
    return v;
}
__device__ __forceinline__ float warpReduceMax(float v) {
    #pragma unroll
    for (int o = 16; o > 0; o >>= 1) v = fmaxf(v, __shfl_down_sync(0xffffffffu, v, o));
    return v;
}
__device__ float blockReduceSum(float v, float* red) {
    int lane = threadIdx.x & 31, wid = threadIdx.x >> 5;
    v = warpReduceSum(v);
    if (lane == 0) red[wid] = v;
    __syncthreads();
    float r = (threadIdx.x < (blockDim.x >> 5)) ? red[threadIdx.x] : 0.f;
    if (wid == 0) r = warpReduceSum(r);
    if (threadIdx.x == 0) red[0] = r;
    __syncthreads();
    r = red[0];
    __syncthreads();
    return r;
}
__device__ float blockReduceMax(float v, float* red) {
    int lane = threadIdx.x & 31, wid = threadIdx.x >> 5;
    v = warpReduceMax(v);
    if (lane == 0) red[wid] = v;
    __syncthreads();
    float r = (threadIdx.x < (blockDim.x >> 5)) ? red[threadIdx.x] : -FLT_MAX;
    if (wid == 0) r = warpReduceMax(r);
    if (threadIdx.x == 0) red[0] = r;
    __syncthreads();
    r = red[0];
    __syncthreads();
    return r;
}

// ---------------- K1: linear layers, split-K GEMM ----------------
__global__ __launch_bounds__(256) void k_linear(const float* __restrict__ x, WPtrs wp) {
    __shared__ float As[16][68];
    __shared__ float Bs[16][68];
    __shared__ const float* colptr[64];

    const int offs[11] = {0,512,516,644,645,773,901,905,906,907,919};
    int bn0 = blockIdx.x * 64, bm0 = blockIdx.y * 64;
    int kbase = blockIdx.z * (INP / SPLITK);
    int tid = threadIdx.x;

    if (tid < 64) {
        int n = bn0 + tid;
        int nn = min(n, NOUT - 1);
        int s = 0;
        #pragma unroll
        for (int i = 0; i < 10; i++) if (nn >= offs[i + 1]) s = i + 1;
        colptr[tid] = wp.W[s] + (size_t)(nn - offs[s]) * INP;
    }
    __syncthreads();

    float acc[4][4];
    #pragma unroll
    for (int i = 0; i < 4; i++)
        #pragma unroll
        for (int j = 0; j < 4; j++) acc[i][j] = 0.f;

    int ty = tid >> 4, tx = tid & 15;
    int li = tid >> 2;
    int lk = (tid & 3) * 4;

    for (int k0 = kbase; k0 < kbase + INP / SPLITK; k0 += 16) {
        float4 xa = *(const float4*)&x[(size_t)(bm0 + li) * INP + k0 + lk];
        float4 wb = *(const float4*)(colptr[li] + k0 + lk);
        As[lk + 0][li] = xa.x; As[lk + 1][li] = xa.y; As[lk + 2][li] = xa.z; As[lk + 3][li] = xa.w;
        Bs[lk + 0][li] = wb.x; Bs[lk + 1][li] = wb.y; Bs[lk + 2][li] = wb.z; Bs[lk + 3][li] = wb.w;
        __syncthreads();
        #pragma unroll
        for (int kk = 0; kk < 16; kk++) {
            float a0 = As[kk][ty * 4 + 0], a1 = As[kk][ty * 4 + 1];
            float a2 = As[kk][ty * 4 + 2], a3 = As[kk][ty * 4 + 3];
            float b0 = Bs[kk][tx * 4 + 0], b1 = Bs[kk][tx * 4 + 1];
            float b2 = Bs[kk][tx * 4 + 2], b3 = Bs[kk][tx * 4 + 3];
            acc[0][0] += a0 * b0; acc[0][1] += a0 * b1; acc[0][2] += a0 * b2; acc[0][3] += a0 * b3;
            acc[1][0] += a1 * b0; acc[1][1] += a1 * b1; acc[1][2] += a1 * b2; acc[1][3] += a1 * b3;
            acc[2][0] += a2 * b0; acc[2][1] += a2 * b1; acc[2][2] += a2 * b2; acc[2][3] += a2 * b3;
            acc[3][0] += a3 * b0; acc[3][1] += a3 * b1; acc[3][2] += a3 * b2; acc[3][3] += a3 * b3;
        }
        __syncthreads();
    }
    float* pz = g_part + (size_t)blockIdx.z * Bb * NOUT;
    #pragma unroll
    for (int i = 0; i < 4; i++) {
        int b = bm0 + ty * 4 + i;
        #pragma unroll
        for (int j = 0; j < 4; j++) {
            int n = bn0 + tx * 4 + j;
            if (n < NOUT) pz[(size_t)b * NOUT + n] = acc[i][j];
        }
    }
}

// ---------------- K1b: bias + activation epilogue ----------------
__global__ __launch_bounds__(256) void k_actep(WPtrs wp) {
    int idx = blockIdx.x * 256 + threadIdx.x;
    if (idx >= Bb * NOUT) return;
    int b = idx / NOUT, n = idx - b * NOUT;
    const int offs[11] = {0,512,516,644,645,773,901,905,906,907,919};
    const int actc[10] = {0,1,0,1,2,0,2,2,2,3};
    int s = 0;
    #pragma unroll
    for (int i = 0; i < 10; i++) if (n >= offs[i + 1]) s = i + 1;
    float v = 0.f;
    #pragma unroll
    for (int z = 0; z < SPLITK; z++) v += g_part[(size_t)z * Bb * NOUT + idx];
    v += wp.bia[s][n - offs[s]];
    int a = actc[s];
    if (a == 0)      v = tanhf(v);
    else if (a == 1) v = (v > 20.f) ? v : log1pf(expf(v));
    else if (a == 2) v = 1.f / (1.f + expf(-v));
    g_act[idx] = v;
}

// ---------------- K2a: write-content scores (split over m) ----------------
__global__ __launch_bounds__(512) void k_wscore(const float* __restrict__ memory) {
    int b = blockIdx.x, s = blockIdx.y, tid = threadIdx.x, lane = tid & 31, wid = tid >> 5;
    __shared__ __align__(16) float wk_s[Ww];
    __shared__ float red[32];
    const float* actb = g_act + (size_t)b * NOUT;
    if (tid < Ww) wk_s[tid] = actb[516 + tid];
    __syncthreads();
    float v = (tid < Ww) ? wk_s[tid] * wk_s[tid] : 0.f;
    float wkn = sqrtf(blockReduceSum(v, red)) + DELTA;
    float wstr = actb[644];

    float4 kv = *(const float4*)&wk_s[lane * 4];
    int m0 = s * (Mm / MSPLIT);
    for (int i = 0; i < (Mm / MSPLIT) / 16; i++) {
        int m = m0 + wid + 16 * i;
        float4 mv = *(const float4*)&memory[((size_t)b * Mm + m) * Ww + lane * 4];
        float d  = mv.x * kv.x + mv.y * kv.y + mv.z * kv.z + mv.w * kv.w;
        float n2 = mv.x * mv.x + mv.y * mv.y + mv.z * mv.z + mv.w * mv.w;
        d = warpReduceSum(d); n2 = warpReduceSum(n2);
        if (lane == 0) {
            float den = (float)Ww * wkn * (sqrtf(n2) + DELTA) + DELTA;
            g_wsc[b * Mm + m] = d / den * wstr;
        }
    }
}

// ---------------- K2b: usage + allocation sort (independent of wsc) ----------------
__global__ __launch_bounds__(512) void k_alloc(const float* __restrict__ read_w,
        const float* __restrict__ write_w, const float* __restrict__ usage_v) {
    int b = blockIdx.x, tid = threadIdx.x, lane = tid & 31, wid = tid >> 5;
    __shared__ float alloc_s[Mm];
    __shared__ unsigned long long key_s[Mm];
    __shared__ float wtot[16], wpre[16];

    const float* actb = g_act + (size_t)b * NOUT;
    float uw  = usage_v[b * Mm + tid];
    float wwr = write_w[b * Mm + tid];
    float u1  = uw + (1.f - uw) * wwr;
    float psi = 1.f;
    #pragma unroll
    for (int r = 0; r < Rr; r++) {
        float fg  = actb[901 + r];
        float rwv = read_w[((size_t)b * Rr + r) * Mm + tid];
        psi *= (1.f - fg * rwv);
    }
    u1 *= psi;
    float uval = DELTA + (1.f - DELTA) * u1;   // > 0, bit-monotonic
    key_s[tid] = ((unsigned long long)__float_as_uint(uval) << 32) | (unsigned)tid;
    __syncthreads();

    // stable bitonic argsort ascending; barrier covers the PREVIOUS stage's span too
    int prevj = 32;
    for (int k = 2; k <= Mm; k <<= 1) {
        for (int j = k >> 1; j > 0; j >>= 1) {
            if (j >= 32 || prevj >= 32) __syncthreads(); else __syncwarp();
            int ixj = tid ^ j;
            if (ixj > tid) {
                unsigned long long a = key_s[tid], bb = key_s[ixj];
                bool up = ((tid & k) == 0);
                if ((a > bb) == up) { key_s[tid] = bb; key_s[ixj] = a; }
            }
            prevj = j;
        }
    }
    __syncthreads();

    unsigned long long kk = key_s[tid];
    float sval = __uint_as_float((unsigned)(kk >> 32));
    int   sidx = (int)(kk & 0xffffffffu);

    float p = sval;
    #pragma unroll
    for (int o = 1; o < 32; o <<= 1) {
        float t = __shfl_up_sync(0xffffffffu, p, o);
        if (lane >= o) p *= t;
    }
    if (lane == 31) wtot[wid] = p;
    __syncthreads();
    if (tid < 16) {
        float v = wtot[tid];
        #pragma unroll
        for (int o = 1; o < 16; o <<= 1) {
            float t = __shfl_up_sync(0x0000ffffu, v, o);
            if (tid >= o) v *= t;
        }
        wpre[tid] = v;
    }
    __syncthreads();
    float warpExcl = (wid == 0) ? 1.f : wpre[wid - 1];
    float prev = __shfl_up_sync(0xffffffffu, p, 1);
    float excl = (lane == 0) ? warpExcl : prev * warpExcl;
    alloc_s[sidx] = (1.f - sval) * excl;
    __syncthreads();

    g_alloc[b * Mm + tid] = alloc_s[tid];
}

// ---------------- K2c: softmax(wsc) + combine with alloc -> ww ----------------
__global__ __launch_bounds__(512) void k_wwcombine() {
    int b = blockIdx.x, tid = threadIdx.x;
    __shared__ float red[32];
    const float* actb = g_act + (size_t)b * NOUT;
    float sc = g_wsc[b * Mm + tid];
    float mx = blockReduceMax(sc, red);
    float e = expf(sc - mx);
    float sum = blockReduceSum(e, red);
    float wcw = e / sum;
    float ag = actb[905], wg = actb[906];
    g_ww[b * Mm + tid] = wg * (ag * g_alloc[b * Mm + tid] + (1.f - ag) * wcw);
}

// ---------------- K3: norms + read-key dots of mem_new (no store; split over m) ----------------
__global__ __launch_bounds__(512) void k_memupdate(const float* __restrict__ memory) {
    int b = blockIdx.x, s = blockIdx.y, tid = threadIdx.x, lane = tid & 31, wid = tid >> 5;
    __shared__ __align__(16) float ev_s[Ww];
    __shared__ __align__(16) float wv_s[Ww];
    __shared__ __align__(16) float rk_s[Rr][Ww];
    const float* actb = g_act + (size_t)b * NOUT;
    if (tid < Ww) { ev_s[tid] = actb[645 + tid]; wv_s[tid] = actb[773 + tid]; }
    rk_s[tid >> 7][tid & 127] = actb[tid];
    __syncthreads();

    float4 e4 = *(const float4*)&ev_s[lane * 4];
    float4 w4 = *(const float4*)&wv_s[lane * 4];
    float4 k0 = *(const float4*)&rk_s[0][lane * 4];
    float4 k1 = *(const float4*)&rk_s[1][lane * 4];
    float4 k2 = *(const float4*)&rk_s[2][lane * 4];
    float4 k3 = *(const float4*)&rk_s[3][lane * 4];

    int m0 = s * (Mm / MSPLIT);
    for (int i = 0; i < (Mm / MSPLIT) / 16; i++) {
        int m = m0 + wid + 16 * i;
        float wwm = g_ww[b * Mm + m];
        size_t off = ((size_t)b * Mm + m) * Ww + lane * 4;
        float4 mv = *(const float4*)&memory[off];
        float4 nv;
        nv.x = mv.x * (1.f - wwm * e4.x) + wwm * w4.x;
        nv.y = mv.y * (1.f - wwm * e4.y) + wwm * w4.y;
        nv.z = mv.z * (1.f - wwm * e4.z) + wwm * w4.z;
        nv.w = mv.w * (1.f - wwm * e4.w) + wwm * w4.w;
        float n2 = nv.x * nv.x + nv.y * nv.y + nv.z * nv.z + nv.w * nv.w;
        float d0 = nv.x * k0.x + nv.y * k0.y + nv.z * k0.z + nv.w * k0.w;
        float d1 = nv.x * k1.x + nv.y * k1.y + nv.z * k1.z + nv.w * k1.w;
        float d2 = nv.x * k2.x + nv.y * k2.y + nv.z * k2.z + nv.w * k2.w;
        float d3 = nv.x * k3.x + nv.y * k3.y + nv.z * k3.z + nv.w * k3.w;
        n2 = warpReduceSum(n2);
        d0 = warpReduceSum(d0); d1 = warpReduceSum(d1);
        d2 = warpReduceSum(d2); d3 = warpReduceSum(d3);
        if (lane == 0) {
            g_norm_new[b * Mm + m] = sqrtf(n2);
            g_dots[((size_t)b * Rr + 0) * Mm + m] = d0;
            g_dots[((size_t)b * Rr + 1) * Mm + m] = d1;
            g_dots[((size_t)b * Rr + 2) * Mm + m] = d2;
            g_dots[((size_t)b * Rr + 3) * Mm + m] = d3;
        }
    }
}

// ---------------- K4: read content weights (softmax) ----------------
__global__ __launch_bounds__(512) void k_readcontent() {
    int r = blockIdx.x, b = blockIdx.y, tid = threadIdx.x;
    __shared__ float red[32];
    const float* actb = g_act + (size_t)b * NOUT;
    float rv = (tid < Ww) ? actb[r * Ww + tid] : 0.f;
    float rkn = sqrtf(blockReduceSum(rv * rv, red)) + DELTA;
    float rs  = actb[512 + r];
    float dot = g_dots[((size_t)b * Rr + r) * Mm + tid];
    float nn  = g_norm_new[b * Mm + tid] + DELTA;
    float sc  = dot / ((float)Ww * rkn * nn + DELTA) * rs;
    float mx  = blockReduceMax(sc, red);
    float e   = expf(sc - mx);
    float sum = blockReduceSum(e, red);
    g_cw[((size_t)b * Rr + r) * Mm + tid] = e / sum;
}

// ---------------- K5: fused link update + fwd/bwd (R9 structure, float4 loads) ----------------
__global__ __launch_bounds__(512) void k_link(const float* __restrict__ LM,
        const float* __restrict__ prec, const float* __restrict__ read_w) {
    int b = blockIdx.x, s = blockIdx.y, tid = threadIdx.x, lane = tid & 31, wid = tid >> 5;
    int c = tid & 127, rr = tid >> 7;   // col-quad, row-subset for the load phase
    __shared__ __align__(16) float Ls[16][Mm];
    __shared__ __align__(16) float4 rw4_s[Mm];
    __shared__ __align__(16) float ww_s[Mm];
    __shared__ __align__(16) float prec_s[Mm];

    {
        float r0 = read_w[((size_t)b * Rr + 0) * Mm + tid];
        float r1 = read_w[((size_t)b * Rr + 1) * Mm + tid];
        float r2 = read_w[((size_t)b * Rr + 2) * Mm + tid];
        float r3 = read_w[((size_t)b * Rr + 3) * Mm + tid];
        rw4_s[tid] = make_float4(r0, r1, r2, r3);
        ww_s[tid]  = g_ww[b * Mm + tid];
        prec_s[tid] = prec[b * Mm + tid];
    }
    __syncthreads();

    float4 wwc = *(const float4*)&ww_s[4 * c];
    float4 prc = *(const float4*)&prec_s[4 * c];

    float4 bacc = make_float4(0.f, 0.f, 0.f, 0.f);
    const float* LMb = LM + (size_t)b * Mm * Mm;
    int row0 = s * (Mm / LSPLIT);                  // 128 rows per block

    for (int t = 0; t < (Mm / LSPLIT) / 16; t++) { // 8 tiles of 16 rows
        #pragma unroll
        for (int pass = 0; pass < 4; pass++) {
            int mm = pass * 4 + rr;
            int row = row0 + t * 16 + mm;
            float4 lm = *(const float4*)&LMb[(size_t)row * Mm + 4 * c];
            float wwrow = ww_s[row];
            float4 lv;
            lv.x = (1.f - wwrow - wwc.x) * lm.x + wwrow * prc.x;
            lv.y = (1.f - wwrow - wwc.y) * lm.y + wwrow * prc.y;
            lv.z = (1.f - wwrow - wwc.z) * lm.z + wwrow * prc.z;
            lv.w = (1.f - wwrow - wwc.w) * lm.w + wwrow * prc.w;
            int d = row - 4 * c;
            if (d == 0) lv.x = 0.f;
            if (d == 1) lv.y = 0.f;
            if (d == 2) lv.z = 0.f;
            if (d == 3) lv.w = 0.f;
            *(float4*)&Ls[mm][4 * c] = lv;
        }
        __syncthreads();
        // bwd: thread owns column n = tid
        #pragma unroll
        for (int mm = 0; mm < 16; mm++) {
            float l = Ls[mm][tid];
            float4 rwm = rw4_s[row0 + t * 16 + mm];
            bacc.x += rwm.x * l; bacc.y += rwm.y * l;
            bacc.z += rwm.z * l; bacc.w += rwm.w * l;
        }
        // fwd: warp wid owns row row0 + t*16 + wid
        {
            float4 f = make_float4(0.f, 0.f, 0.f, 0.f);
            #pragma unroll
            for (int i = 0; i < 16; i++) {
                float l = Ls[wid][lane + 32 * i];
                float4 rv = rw4_s[lane + 32 * i];
                f.x += l * rv.x; f.y += l * rv.y;
                f.z += l * rv.z; f.w += l * rv.w;
            }
            f.x = warpReduceSum(f.x); f.y = warpReduceSum(f.y);
            f.z = warpReduceSum(f.z); f.w = warpReduceSum(f.w);
            if (lane == 0) {
                int row = row0 + t * 16 + wid;
                g_fwd[((size_t)b * Rr + 0) * Mm + row] = f.x;
                g_fwd[((size_t)b * Rr + 1) * Mm + row] = f.y;
                g_fwd[((size_t)b * Rr + 2) * Mm + row] = f.z;
                g_fwd[((size_t)b * Rr + 3) * Mm + row] = f.w;
            }
        }
        __syncthreads();
    }
    size_t pb = (size_t)s * Bb * Rr * Mm + (size_t)b * Rr * Mm;
    g_bwdp[pb + 0 * Mm + tid] = bacc.x;
    g_bwdp[pb + 1 * Mm + tid] = bacc.y;
    g_bwdp[pb + 2 * Mm + tid] = bacc.z;
    g_bwdp[pb + 3 * Mm + tid] = bacc.w;
}

// ---------------- K6: rw_new + read vectors; mem_new recomputed inline ----------------
__global__ __launch_bounds__(512) void k_final(const float* __restrict__ memory) {
    int b = blockIdx.x, s = blockIdx.y, tid = threadIdx.x;
    __shared__ float rwn_s[512];
    __shared__ float rm_s[Rr][3];
    __shared__ float ww_sh[128];
    __shared__ float ev_sh[Ww];
    __shared__ float wv_sh[Ww];
    const float* actb = g_act + (size_t)b * NOUT;
    int m0 = s * (Mm / FSPLIT);
    if (tid < Rr) {
        float l0 = actb[907 + tid * 3 + 0];
        float l1 = actb[907 + tid * 3 + 1];
        float l2 = actb[907 + tid * 3 + 2];
        float mx = fmaxf(l0, fmaxf(l1, l2));
        float e0 = expf(l0 - mx), e1 = expf(l1 - mx), e2 = expf(l2 - mx);
        float sm = e0 + e1 + e2;
        rm_s[tid][0] = e0 / sm; rm_s[tid][1] = e1 / sm; rm_s[tid][2] = e2 / sm;
    }
    if (tid < 128)                    ww_sh[tid]       = g_ww[b * Mm + m0 + tid];
    else if (tid < 256)               ev_sh[tid - 128] = actb[645 + tid - 128];
    else if (tid < 384)               wv_sh[tid - 256] = actb[773 + tid - 256];
    __syncthreads();
    {
        int r = tid >> 7, mm = tid & 127;
        size_t o = ((size_t)b * Rr + r) * Mm + m0 + mm;
        float bwd = 0.f;
        #pragma unroll
        for (int z = 0; z < LSPLIT; z++) bwd += g_bwdp[(size_t)z * Bb * Rr * Mm + o];
        rwn_s[tid] = rm_s[r][0] * bwd + rm_s[r][1] * g_fwd[o] + rm_s[r][2] * g_cw[o];
    }
    __syncthreads();
    int r = tid >> 7, w = tid & 127;
    float evw = ev_sh[w], wvw = wv_sh[w];
    const float* mb = memory + ((size_t)b * Mm + m0) * Ww;
    float acc = 0.f;
    #pragma unroll 8
    for (int mm = 0; mm < Mm / FSPLIT; mm++) {
        float wwm = ww_sh[mm];
        float mv  = mb[(size_t)mm * Ww + w];
        float nv  = mv * (1.f - wwm * evw) + wwm * wvw;   // mem_new recomputed
        acc += rwn_s[r * 128 + mm] * nv;
    }
    g_outp[(size_t)s * Bb * Rr * Ww + ((size_t)b * Rr + r) * Ww + w] = acc;
}

// ---------------- K6c: sum output partials ----------------
__global__ __launch_bounds__(256) void k_outsum(float* __restrict__ out) {
    int i = blockIdx.x * 256 + threadIdx.x;
    if (i >= Bb * Rr * Ww) return;
    float v = 0.f;
    #pragma unroll
    for (int z = 0; z < FSPLIT; z++) v += g_outp[(size_t)z * Bb * Rr * Ww + i];
    out[i] = v;
}

// ---------------- launch: double fork-join ----------------
extern "C" void kernel_launch(void* const* d_in, const int* in_sizes, int n_in,
                              void* d_out, int out_size) {
    const float* x      = (const float*)d_in[0];
    const float* memory = (const float*)d_in[1];
    const float* LM     = (const float*)d_in[2];
    const float* prec   = (const float*)d_in[3];
    const float* rw     = (const float*)d_in[4];
    const float* wwr    = (const float*)d_in[5];
    const float* usage  = (const float*)d_in[6];
    WPtrs wp;
    for (int i = 0; i < 10; i++) {
        wp.W[i]   = (const float*)d_in[7 + 2 * i];
        wp.bia[i] = (const float*)d_in[8 + 2 * i];
    }

    cudaStream_t sB;
    cudaEvent_t eFork0, eW, eFork, eJoin;
    cudaStreamCreateWithFlags(&sB, cudaStreamNonBlocking);
    cudaEventCreateWithFlags(&eFork0, cudaEventDisableTiming);
    cudaEventCreateWithFlags(&eW, cudaEventDisableTiming);
    cudaEventCreateWithFlags(&eFork, cudaEventDisableTiming);
    cudaEventCreateWithFlags(&eJoin, cudaEventDisableTiming);

    k_linear<<<dim3(15, 2, SPLITK), 256>>>(x, wp);
    k_actep<<<(Bb * NOUT + 255) / 256, 256>>>(wp);

    // fork 1: wscore (memory scan) on sB, alloc (sort) on main
    cudaEventRecord(eFork0, 0);
    cudaStreamWaitEvent(sB, eFork0, 0);
    k_wscore<<<dim3(Bb, MSPLIT), 512, 0, sB>>>(memory);
    cudaEventRecord(eW, sB);

    k_alloc<<<Bb, 512>>>(rw, wwr, usage);

    cudaStreamWaitEvent(0, eW, 0);          // join 1
    k_wwcombine<<<Bb, 512>>>();

    // fork 2: branch B (memupdate -> readcontent) beside k_link
    cudaEventRecord(eFork, 0);
    cudaStreamWaitEvent(sB, eFork, 0);
    k_memupdate<<<dim3(Bb, MSPLIT), 512, 0, sB>>>(memory);
    k_readcontent<<<dim3(Rr, Bb), 512, 0, sB>>>();
    cudaEventRecord(eJoin, sB);

    k_link<<<dim3(Bb, LSPLIT), 512>>>(LM, prec, rw);

    cudaStreamWaitEvent(0, eJoin, 0);       // join 2
    k_final<<<dim3(Bb, FSPLIT), 512>>>(memory);
    k_outsum<<<(Bb * Rr * Ww + 255) / 256, 256>>>((float*)d_out);
}

// round 15
// speedup vs baseline: 1.0550x; 1.0550x over previous
#include <cuda_runtime.h>
#include <math.h>
#include <float.h>

#define DELTA 1e-6f
#define Bb 128
#define Mm 512
#define Ww 128
#define Rr 4
#define INP 1024
#define NOUT 919
#define SPLITK 8
#define LSPLIT 4
#define MSPLIT 4
#define FSPLIT 4

// ---------------- scratch (static device globals; no allocation) ----------------
__device__ float g_part[SPLITK * Bb * NOUT];
__device__ float g_wsc[Bb * Mm];
__device__ float g_ww[Bb * Mm];
__device__ float g_norm_new[Bb * Mm];
__device__ float g_dots[Bb * Rr * Mm];
__device__ float g_cw[Bb * Rr * Mm];
__device__ float g_fwd[Bb * Rr * Mm];
__device__ float g_bwdp[(size_t)LSPLIT * Bb * Rr * Mm];

struct WPtrs { const float* W[10]; const float* bia[10]; };

// ---------------- inline linear-output reconstruction (replaces k_actep) ----------------
// Sums the SPLITK partials in the SAME order k_actep did -> bit-identical.
__device__ __forceinline__ float linsum(int b, int n) {
    float v = 0.f;
    #pragma unroll
    for (int z = 0; z < SPLITK; z++)
        v += g_part[(size_t)z * Bb * NOUT + (size_t)b * NOUT + n];
    return v;
}
__device__ __forceinline__ float act_tanh(int b, int n, const float* bia, int i) {
    return tanhf(linsum(b, n) + bia[i]);
}
__device__ __forceinline__ float act_sigm(int b, int n, const float* bia, int i) {
    return 1.f / (1.f + expf(-(linsum(b, n) + bia[i])));
}
__device__ __forceinline__ float act_sftp(int b, int n, const float* bia, int i) {
    float v = linsum(b, n) + bia[i];
    return (v > 20.f) ? v : log1pf(expf(v));
}

// ---------------- reductions ----------------
__device__ __forceinline__ float warpReduceSum(float v) {
    #pragma unroll
    for (int o = 16; o > 0; o >>= 1) v += __shfl_down_sync(0xffffffffu, v, o);
    return v;
}
__device__ __forceinline__ float warpReduceMax(float v) {
    #pragma unroll
    for (int o = 16; o > 0; o >>= 1) v = fmaxf(v, __shfl_down_sync(0xffffffffu, v, o));
    return v;
}
__device__ float blockReduceSum(float v, float* red) {
    int lane = threadIdx.x & 31, wid = threadIdx.x >> 5;
    v = warpReduceSum(v);
    if (lane == 0) red[wid] = v;
    __syncthreads();
    float r = (threadIdx.x < (blockDim.x >> 5)) ? red[threadIdx.x] : 0.f;
    if (wid == 0) r = warpReduceSum(r);
    if (threadIdx.x == 0) red[0] = r;
    __syncthreads();
    r = red[0];
    __syncthreads();
    return r;
}
__device__ float blockReduceMax(float v, float* red) {
    int lane = threadIdx.x & 31, wid = threadIdx.x >> 5;
    v = warpReduceMax(v);
    if (lane == 0) red[wid] = v;
    __syncthreads();
    float r = (threadIdx.x < (blockDim.x >> 5)) ? red[threadIdx.x] : -FLT_MAX;
    if (wid == 0) r = warpReduceMax(r);
    if (threadIdx.x == 0) red[0] = r;
    __syncthreads();
    r = red[0];
    __syncthreads();
    return r;
}

// ---------------- K0: zero the output (on side stream, INSIDE capture) ----------------
__global__ __launch_bounds__(256) void k_zero(float* __restrict__ out) {
    int i = blockIdx.x * 256 + threadIdx.x;
    if (i < Bb * Rr * Ww) out[i] = 0.f;
}

// ---------------- K1: linear layers, split-K GEMM ----------------
__global__ __launch_bounds__(256) void k_linear(const float* __restrict__ x, WPtrs wp) {
    __shared__ float As[16][68];
    __shared__ float Bs[16][68];
    __shared__ const float* colptr[64];

    const int offs[11] = {0,512,516,644,645,773,901,905,906,907,919};
    int bn0 = blockIdx.x * 64, bm0 = blockIdx.y * 64;
    int kbase = blockIdx.z * (INP / SPLITK);
    int tid = threadIdx.x;

    if (tid < 64) {
        int n = bn0 + tid;
        int nn = min(n, NOUT - 1);
        int s = 0;
        #pragma unroll
        for (int i = 0; i < 10; i++) if (nn >= offs[i + 1]) s = i + 1;
        colptr[tid] = wp.W[s] + (size_t)(nn - offs[s]) * INP;
    }
    __syncthreads();

    float acc[4][4];
    #pragma unroll
    for (int i = 0; i < 4; i++)
        #pragma unroll
        for (int j = 0; j < 4; j++) acc[i][j] = 0.f;

    int ty = tid >> 4, tx = tid & 15;
    int li = tid >> 2;
    int lk = (tid & 3) * 4;

    for (int k0 = kbase; k0 < kbase + INP / SPLITK; k0 += 16) {
        float4 xa = *(const float4*)&x[(size_t)(bm0 + li) * INP + k0 + lk];
        float4 wb = *(const float4*)(colptr[li] + k0 + lk);
        As[lk + 0][li] = xa.x; As[lk + 1][li] = xa.y; As[lk + 2][li] = xa.z; As[lk + 3][li] = xa.w;
        Bs[lk + 0][li] = wb.x; Bs[lk + 1][li] = wb.y; Bs[lk + 2][li] = wb.z; Bs[lk + 3][li] = wb.w;
        __syncthreads();
        #pragma unroll
        for (int kk = 0; kk < 16; kk++) {
            float a0 = As[kk][ty * 4 + 0], a1 = As[kk][ty * 4 + 1];
            float a2 = As[kk][ty * 4 + 2], a3 = As[kk][ty * 4 + 3];
            float b0 = Bs[kk][tx * 4 + 0], b1 = Bs[kk][tx * 4 + 1];
            float b2 = Bs[kk][tx * 4 + 2], b3 = Bs[kk][tx * 4 + 3];
            acc[0][0] += a0 * b0; acc[0][1] += a0 * b1; acc[0][2] += a0 * b2; acc[0][3] += a0 * b3;
            acc[1][0] += a1 * b0; acc[1][1] += a1 * b1; acc[1][2] += a1 * b2; acc[1][3] += a1 * b3;
            acc[2][0] += a2 * b0; acc[2][1] += a2 * b1; acc[2][2] += a2 * b2; acc[2][3] += a2 * b3;
            acc[3][0] += a3 * b0; acc[3][1] += a3 * b1; acc[3][2] += a3 * b2; acc[3][3] += a3 * b3;
        }
        __syncthreads();
    }
    float* pz = g_part + (size_t)blockIdx.z * Bb * NOUT;
    #pragma unroll
    for (int i = 0; i < 4; i++) {
        int b = bm0 + ty * 4 + i;
        #pragma unroll
        for (int j = 0; j < 4; j++) {
            int n = bn0 + tx * 4 + j;
            if (n < NOUT) pz[(size_t)b * NOUT + n] = acc[i][j];
        }
    }
}

// ---------------- K2a: write-content scores (split over m; inline act) ----------------
__global__ __launch_bounds__(512) void k_wscore(const float* __restrict__ memory,
        const float* __restrict__ b_wk, const float* __restrict__ b_ws) {
    int b = blockIdx.x, s = blockIdx.y, tid = threadIdx.x, lane = tid & 31, wid = tid >> 5;
    __shared__ __align__(16) float wk_s[Ww];
    __shared__ float red[32];
    if (tid < Ww) wk_s[tid] = act_tanh(b, 516 + tid, b_wk, tid);
    __syncthreads();
    float v = (tid < Ww) ? wk_s[tid] * wk_s[tid] : 0.f;
    float wkn = sqrtf(blockReduceSum(v, red)) + DELTA;
    float wstr = act_sftp(b, 644, b_ws, 0);

    float4 kv = *(const float4*)&wk_s[lane * 4];
    int m0 = s * (Mm / MSPLIT);
    for (int i = 0; i < (Mm / MSPLIT) / 16; i++) {
        int m = m0 + wid + 16 * i;
        float4 mv = *(const float4*)&memory[((size_t)b * Mm + m) * Ww + lane * 4];
        float d  = mv.x * kv.x + mv.y * kv.y + mv.z * kv.z + mv.w * kv.w;
        float n2 = mv.x * mv.x + mv.y * mv.y + mv.z * mv.z + mv.w * mv.w;
        d = warpReduceSum(d); n2 = warpReduceSum(n2);
        if (lane == 0) {
            float den = (float)Ww * wkn * (sqrtf(n2) + DELTA) + DELTA;
            g_wsc[b * Mm + m] = d / den * wstr;
        }
    }
}

// ---------------- K2b: softmax + usage + allocation sort + ww (inline act) ----------------
__global__ __launch_bounds__(512) void k_writehead(const float* __restrict__ read_w,
        const float* __restrict__ write_w, const float* __restrict__ usage_v,
        const float* __restrict__ b_fg, const float* __restrict__ b_ag,
        const float* __restrict__ b_wg) {
    int b = blockIdx.x, tid = threadIdx.x, lane = tid & 31, wid = tid >> 5;
    __shared__ float wcw_s[Mm];
    __shared__ float alloc_s[Mm];
    __shared__ unsigned long long key_s[Mm];
    __shared__ float red[32];
    __shared__ float wtot[16], wpre[16];
    __shared__ float sc6[6];   // fg0..3, ag, wg

    if (tid < 4)       sc6[tid] = act_sigm(b, 901 + tid, b_fg, tid);
    else if (tid == 4) sc6[4]   = act_sigm(b, 905, b_ag, 0);
    else if (tid == 5) sc6[5]   = act_sigm(b, 906, b_wg, 0);
    __syncthreads();

    float sc = g_wsc[b * Mm + tid];
    float mx = blockReduceMax(sc, red);
    float e = expf(sc - mx);
    float sum = blockReduceSum(e, red);
    wcw_s[tid] = e / sum;

    float uw  = usage_v[b * Mm + tid];
    float wwr = write_w[b * Mm + tid];
    float u1  = uw + (1.f - uw) * wwr;
    float psi = 1.f;
    #pragma unroll
    for (int r = 0; r < Rr; r++) {
        float rwv = read_w[((size_t)b * Rr + r) * Mm + tid];
        psi *= (1.f - sc6[r] * rwv);
    }
    u1 *= psi;
    float uval = DELTA + (1.f - DELTA) * u1;   // > 0, bit-monotonic
    key_s[tid] = ((unsigned long long)__float_as_uint(uval) << 32) | (unsigned)tid;
    __syncthreads();

    // stable bitonic argsort ascending; barrier covers the PREVIOUS stage's span too
    int prevj = 32;
    for (int k = 2; k <= Mm; k <<= 1) {
        for (int j = k >> 1; j > 0; j >>= 1) {
            if (j >= 32 || prevj >= 32) __syncthreads(); else __syncwarp();
            int ixj = tid ^ j;
            if (ixj > tid) {
                unsigned long long a = key_s[tid], bb = key_s[ixj];
                bool up = ((tid & k) == 0);
                if ((a > bb) == up) { key_s[tid] = bb; key_s[ixj] = a; }
            }
            prevj = j;
        }
    }
    __syncthreads();

    unsigned long long kk = key_s[tid];
    float sval = __uint_as_float((unsigned)(kk >> 32));
    int   sidx = (int)(kk & 0xffffffffu);

    float p = sval;
    #pragma unroll
    for (int o = 1; o < 32; o <<= 1) {
        float t = __shfl_up_sync(0xffffffffu, p, o);
        if (lane >= o) p *= t;
    }
    if (lane == 31) wtot[wid] = p;
    __syncthreads();
    if (tid < 16) {
        float v = wtot[tid];
        #pragma unroll
        for (int o = 1; o < 16; o <<= 1) {
            float t = __shfl_up_sync(0x0000ffffu, v, o);
            if (tid >= o) v *= t;
        }
        wpre[tid] = v;
    }
    __syncthreads();
    float warpExcl = (wid == 0) ? 1.f : wpre[wid - 1];
    float prev = __shfl_up_sync(0xffffffffu, p, 1);
    float excl = (lane == 0) ? warpExcl : prev * warpExcl;
    alloc_s[sidx] = (1.f - sval) * excl;
    __syncthreads();

    float ag = sc6[4], wg = sc6[5];
    g_ww[b * Mm + tid] = wg * (ag * alloc_s[tid] + (1.f - ag) * wcw_s[tid]);
}

// ---------------- K3: norms + read-key dots of mem_new (inline act) ----------------
__global__ __launch_bounds__(512) void k_memupdate(const float* __restrict__ memory,
        const float* __restrict__ b_ev, const float* __restrict__ b_wv,
        const float* __restrict__ b_rk) {
    int b = blockIdx.x, s = blockIdx.y, tid = threadIdx.x, lane = tid & 31, wid = tid >> 5;
    __shared__ __align__(16) float ev_s[Ww];
    __shared__ __align__(16) float wv_s[Ww];
    __shared__ __align__(16) float rk_s[Rr][Ww];
    if (tid < Ww) {
        ev_s[tid] = act_sigm(b, 645 + tid, b_ev, tid);
        wv_s[tid] = act_tanh(b, 773 + tid, b_wv, tid);
    }
    rk_s[tid >> 7][tid & 127] = act_tanh(b, tid, b_rk, tid);
    __syncthreads();

    float4 e4 = *(const float4*)&ev_s[lane * 4];
    float4 w4 = *(const float4*)&wv_s[lane * 4];
    float4 k0 = *(const float4*)&rk_s[0][lane * 4];
    float4 k1 = *(const float4*)&rk_s[1][lane * 4];
    float4 k2 = *(const float4*)&rk_s[2][lane * 4];
    float4 k3 = *(const float4*)&rk_s[3][lane * 4];

    int m0 = s * (Mm / MSPLIT);
    for (int i = 0; i < (Mm / MSPLIT) / 16; i++) {
        int m = m0 + wid + 16 * i;
        float wwm = g_ww[b * Mm + m];
        size_t off = ((size_t)b * Mm + m) * Ww + lane * 4;
        float4 mv = *(const float4*)&memory[off];
        float4 nv;
        nv.x = mv.x * (1.f - wwm * e4.x) + wwm * w4.x;
        nv.y = mv.y * (1.f - wwm * e4.y) + wwm * w4.y;
        nv.z = mv.z * (1.f - wwm * e4.z) + wwm * w4.z;
        nv.w = mv.w * (1.f - wwm * e4.w) + wwm * w4.w;
        float n2 = nv.x * nv.x + nv.y * nv.y + nv.z * nv.z + nv.w * nv.w;
        float d0 = nv.x * k0.x + nv.y * k0.y + nv.z * k0.z + nv.w * k0.w;
        float d1 = nv.x * k1.x + nv.y * k1.y + nv.z * k1.z + nv.w * k1.w;
        float d2 = nv.x * k2.x + nv.y * k2.y + nv.z * k2.z + nv.w * k2.w;
        float d3 = nv.x * k3.x + nv.y * k3.y + nv.z * k3.z + nv.w * k3.w;
        n2 = warpReduceSum(n2);
        d0 = warpReduceSum(d0); d1 = warpReduceSum(d1);
        d2 = warpReduceSum(d2); d3 = warpReduceSum(d3);
        if (lane == 0) {
            g_norm_new[b * Mm + m] = sqrtf(n2);
            g_dots[((size_t)b * Rr + 0) * Mm + m] = d0;
            g_dots[((size_t)b * Rr + 1) * Mm + m] = d1;
            g_dots[((size_t)b * Rr + 2) * Mm + m] = d2;
            g_dots[((size_t)b * Rr + 3) * Mm + m] = d3;
        }
    }
}

// ---------------- K4: read content weights (softmax; inline act) ----------------
__global__ __launch_bounds__(512) void k_readcontent(const float* __restrict__ b_rk,
        const float* __restrict__ b_rs) {
    int r = blockIdx.x, b = blockIdx.y, tid = threadIdx.x;
    __shared__ float red[32];
    float rv = (tid < Ww) ? act_tanh(b, r * Ww + tid, b_rk, r * Ww + tid) : 0.f;
    float rkn = sqrtf(blockReduceSum(rv * rv, red)) + DELTA;
    float rs  = act_sftp(b, 512 + r, b_rs, r);
    float dot = g_dots[((size_t)b * Rr + r) * Mm + tid];
    float nn  = g_norm_new[b * Mm + tid] + DELTA;
    float sc  = dot / ((float)Ww * rkn * nn + DELTA) * rs;
    float mx  = blockReduceMax(sc, red);
    float e   = expf(sc - mx);
    float sum = blockReduceSum(e, red);
    g_cw[((size_t)b * Rr + r) * Mm + tid] = e / sum;
}

// ---------------- K5: fused link update + fwd/bwd (R9 structure, float4 loads) ----------------
__global__ __launch_bounds__(512) void k_link(const float* __restrict__ LM,
        const float* __restrict__ prec, const float* __restrict__ read_w) {
    int b = blockIdx.x, s = blockIdx.y, tid = threadIdx.x, lane = tid & 31, wid = tid >> 5;
    int c = tid & 127, rr = tid >> 7;
    __shared__ __align__(16) float Ls[16][Mm];
    __shared__ __align__(16) float4 rw4_s[Mm];
    __shared__ __align__(16) float ww_s[Mm];
    __shared__ __align__(16) float prec_s[Mm];

    {
        float r0 = read_w[((size_t)b * Rr + 0) * Mm + tid];
        float r1 = read_w[((size_t)b * Rr + 1) * Mm + tid];
        float r2 = read_w[((size_t)b * Rr + 2) * Mm + tid];
        float r3 = read_w[((size_t)b * Rr + 3) * Mm + tid];
        rw4_s[tid] = make_float4(r0, r1, r2, r3);
        ww_s[tid]  = g_ww[b * Mm + tid];
        prec_s[tid] = prec[b * Mm + tid];
    }
    __syncthreads();

    float4 wwc = *(const float4*)&ww_s[4 * c];
    float4 prc = *(const float4*)&prec_s[4 * c];

    float4 bacc = make_float4(0.f, 0.f, 0.f, 0.f);
    const float* LMb = LM + (size_t)b * Mm * Mm;
    int row0 = s * (Mm / LSPLIT);

    for (int t = 0; t < (Mm / LSPLIT) / 16; t++) {
        #pragma unroll
        for (int pass = 0; pass < 4; pass++) {
            int mm = pass * 4 + rr;
            int row = row0 + t * 16 + mm;
            float4 lm = *(const float4*)&LMb[(size_t)row * Mm + 4 * c];
            float wwrow = ww_s[row];
            float4 lv;
            lv.x = (1.f - wwrow - wwc.x) * lm.x + wwrow * prc.x;
            lv.y = (1.f - wwrow - wwc.y) * lm.y + wwrow * prc.y;
            lv.z = (1.f - wwrow - wwc.z) * lm.z + wwrow * prc.z;
            lv.w = (1.f - wwrow - wwc.w) * lm.w + wwrow * prc.w;
            int d = row - 4 * c;
            if (d == 0) lv.x = 0.f;
            if (d == 1) lv.y = 0.f;
            if (d == 2) lv.z = 0.f;
            if (d == 3) lv.w = 0.f;
            *(float4*)&Ls[mm][4 * c] = lv;
        }
        __syncthreads();
        #pragma unroll
        for (int mm = 0; mm < 16; mm++) {
            float l = Ls[mm][tid];
            float4 rwm = rw4_s[row0 + t * 16 + mm];
            bacc.x += rwm.x * l; bacc.y += rwm.y * l;
            bacc.z += rwm.z * l; bacc.w += rwm.w * l;
        }
        {
            float4 f = make_float4(0.f, 0.f, 0.f, 0.f);
            #pragma unroll
            for (int i = 0; i < 16; i++) {
                float l = Ls[wid][lane + 32 * i];
                float4 rv = rw4_s[lane + 32 * i];
                f.x += l * rv.x; f.y += l * rv.y;
                f.z += l * rv.z; f.w += l * rv.w;
            }
            f.x = warpReduceSum(f.x); f.y = warpReduceSum(f.y);
            f.z = warpReduceSum(f.z); f.w = warpReduceSum(f.w);
            if (lane == 0) {
                int row = row0 + t * 16 + wid;
                g_fwd[((size_t)b * Rr + 0) * Mm + row] = f.x;
                g_fwd[((size_t)b * Rr + 1) * Mm + row] = f.y;
                g_fwd[((size_t)b * Rr + 2) * Mm + row] = f.z;
                g_fwd[((size_t)b * Rr + 3) * Mm + row] = f.w;
            }
        }
        __syncthreads();
    }
    size_t pb = (size_t)s * Bb * Rr * Mm + (size_t)b * Rr * Mm;
    g_bwdp[pb + 0 * Mm + tid] = bacc.x;
    g_bwdp[pb + 1 * Mm + tid] = bacc.y;
    g_bwdp[pb + 2 * Mm + tid] = bacc.z;
    g_bwdp[pb + 3 * Mm + tid] = bacc.w;
}

// ---------------- K6: rw_new + read vectors; mem_new inline; atomicAdd to out ----------------
__global__ __launch_bounds__(512) void k_final(const float* __restrict__ memory,
        float* __restrict__ out, const float* __restrict__ b_rm,
        const float* __restrict__ b_ev, const float* __restrict__ b_wv) {
    int b = blockIdx.x, s = blockIdx.y, tid = threadIdx.x;
    __shared__ float rwn_s[512];
    __shared__ float rm_s[Rr][3];
    __shared__ float ww_sh[128];
    __shared__ float ev_sh[Ww];
    __shared__ float wv_sh[Ww];
    int m0 = s * (Mm / FSPLIT);
    if (tid < Rr) {
        float l0 = linsum(b, 907 + tid * 3 + 0) + b_rm[tid * 3 + 0];
        float l1 = linsum(b, 907 + tid * 3 + 1) + b_rm[tid * 3 + 1];
        float l2 = linsum(b, 907 + tid * 3 + 2) + b_rm[tid * 3 + 2];
        float mx = fmaxf(l0, fmaxf(l1, l2));
        float e0 = expf(l0 - mx), e1 = expf(l1 - mx), e2 = expf(l2 - mx);
        float sm = e0 + e1 + e2;
        rm_s[tid][0] = e0 / sm; rm_s[tid][1] = e1 / sm; rm_s[tid][2] = e2 / sm;
    }
    if (tid < 128)       ww_sh[tid]       = g_ww[b * Mm + m0 + tid];
    else if (tid < 256)  ev_sh[tid - 128] = act_sigm(b, 645 + tid - 128, b_ev, tid - 128);
    else if (tid < 384)  wv_sh[tid - 256] = act_tanh(b, 773 + tid - 256, b_wv, tid - 256);
    __syncthreads();
    {
        int r = tid >> 7, mm = tid & 127;
        size_t o = ((size_t)b * Rr + r) * Mm + m0 + mm;
        float bwd = 0.f;
        #pragma unroll
        for (int z = 0; z < LSPLIT; z++) bwd += g_bwdp[(size_t)z * Bb * Rr * Mm + o];
        rwn_s[tid] = rm_s[r][0] * bwd + rm_s[r][1] * g_fwd[o] + rm_s[r][2] * g_cw[o];
    }
    __syncthreads();
    int r = tid >> 7, w = tid & 127;
    float evw = ev_sh[w], wvw = wv_sh[w];
    const float* mb = memory + ((size_t)b * Mm + m0) * Ww;
    float acc = 0.f;
    #pragma unroll 8
    for (int mm = 0; mm < Mm / FSPLIT; mm++) {
        float wwm = ww_sh[mm];
        float mv  = mb[(size_t)mm * Ww + w];
        float nv  = mv * (1.f - wwm * evw) + wwm * wvw;
        acc += rwn_s[r * 128 + mm] * nv;
    }
    atomicAdd(&out[((size_t)b * Rr + r) * Ww + w], acc);
}

// ---------------- launch: fork-join; side stream joined to capture BEFORE k_zero ----------------
extern "C" void kernel_launch(void* const* d_in, const int* in_sizes, int n_in,
                              void* d_out, int out_size) {
    const float* x      = (const float*)d_in[0];
    const float* memory = (const float*)d_in[1];
    const float* LM     = (const float*)d_in[2];
    const float* prec   = (const float*)d_in[3];
    const float* rw     = (const float*)d_in[4];
    const float* wwr    = (const float*)d_in[5];
    const float* usage  = (const float*)d_in[6];
    WPtrs wp;
    for (int i = 0; i < 10; i++) {
        wp.W[i]   = (const float*)d_in[7 + 2 * i];
        wp.bia[i] = (const float*)d_in[8 + 2 * i];
    }
    // bias index map: 0 rk, 1 rs, 2 wk, 3 ws, 4 ev, 5 wv, 6 fg, 7 ag, 8 wg, 9 rm
    const float *b_rk = wp.bia[0], *b_rs = wp.bia[1], *b_wk = wp.bia[2], *b_ws = wp.bia[3];
    const float *b_ev = wp.bia[4], *b_wv = wp.bia[5], *b_fg = wp.bia[6], *b_ag = wp.bia[7];
    const float *b_wg = wp.bia[8], *b_rm = wp.bia[9];

    cudaStream_t sB;
    cudaEvent_t eStart, eFork, eJoin;
    cudaStreamCreateWithFlags(&sB, cudaStreamNonBlocking);
    cudaEventCreateWithFlags(&eStart, cudaEventDisableTiming);
    cudaEventCreateWithFlags(&eFork, cudaEventDisableTiming);
    cudaEventCreateWithFlags(&eJoin, cudaEventDisableTiming);

    // Join sB into the capture FIRST so everything on it is inside the graph.
    cudaEventRecord(eStart, 0);
    cudaStreamWaitEvent(sB, eStart, 0);
    // d_out zeroing on the (captured) side stream; ordered before k_final via
    // the sB program order (k_zero -> memupdate -> readcontent -> eJoin).
    k_zero<<<(Bb * Rr * Ww + 255) / 256, 256, 0, sB>>>((float*)d_out);

    k_linear<<<dim3(15, 2, SPLITK), 256>>>(x, wp);
    k_wscore<<<dim3(Bb, MSPLIT), 512>>>(memory, b_wk, b_ws);
    k_writehead<<<Bb, 512>>>(rw, wwr, usage, b_fg, b_ag, b_wg);

    // fork: branch B (memupdate -> readcontent) runs beside k_link
    cudaEventRecord(eFork, 0);
    cudaStreamWaitEvent(sB, eFork, 0);
    k_memupdate<<<dim3(Bb, MSPLIT), 512, 0, sB>>>(memory, b_ev, b_wv, b_rk);
    k_readcontent<<<dim3(Rr, Bb), 512, 0, sB>>>(b_rk, b_rs);
    cudaEventRecord(eJoin, sB);

    k_link<<<dim3(Bb, LSPLIT), 512>>>(LM, prec, rw);

    cudaStreamWaitEvent(0, eJoin, 0);
    k_final<<<dim3(Bb, FSPLIT), 512>>>(memory, (float*)d_out, b_rm, b_ev, b_wv);
}